// round 1
// baseline (speedup 1.0000x reference)
#include <cuda_runtime.h>
#include <math.h>

#define B_SZ 32768
#define DIN 256
#define SDIM_ 12
#define BK 16
#define ASTR 132
#define NCK 192   /* 3072 / BK */

// Scratch activations (allocation-free requirement -> __device__ globals)
__device__ float g_buf0[(size_t)B_SZ * DIN];
__device__ float g_buf1[(size_t)B_SZ * DIN];

__constant__ float c_knots[8] = {
    1.0f/9.0f, 2.0f/9.0f, 3.0f/9.0f, 4.0f/9.0f,
    5.0f/9.0f, 6.0f/9.0f, 7.0f/9.0f, 8.0f/9.0f
};

__device__ __forceinline__ void basis_eval(float t, float* bb){
    bb[0] = 1.0f;
    bb[1] = t;
    bb[2] = t * t;
    bb[3] = bb[2] * t;
#pragma unroll
    for (int j = 0; j < 8; j++){
        float d = fmaxf(t - c_knots[j], 0.0f);
        bb[4 + j] = d * d * d;
    }
}

// C(32768 x 256) = A(32768 x 3072) * W(3072 x 256) + basis @ Bv, optional relu.
// A[b, s*256+i] = basis[b,s] * X[b,i], built on the fly while loading tiles.
template<bool RELU>
__global__ __launch_bounds__(256, 2)
void vc_gemm(const float* __restrict__ T, const float* __restrict__ X,
             const float* __restrict__ W, const float* __restrict__ Bv,
             float* __restrict__ Y)
{
    __shared__ float As[BK * ASTR];     // transposed: As[k][row], pad 132
    __shared__ float Bs[BK * 128];      // Bs[k][col]
    __shared__ float sbias[SDIM_ * 128];
    __shared__ float sbasis[128 * SDIM_];

    const int tid = threadIdx.x;
    const int m0 = blockIdx.y * 128;
    const int n0 = blockIdx.x * 128;

    if (tid < 128){
        float bb[12];
        basis_eval(T[m0 + tid], bb);
#pragma unroll
        for (int s = 0; s < 12; s++) sbasis[tid * 12 + s] = bb[s];
    }
    for (int idx = tid; idx < 12 * 128; idx += 256){
        sbias[idx] = Bv[(idx >> 7) * 256 + n0 + (idx & 127)];
    }

    const int a_r  = tid >> 2;   // 0..63 (+64)
    const int a_c4 = tid & 3;    // which float4 in the 16-wide k-chunk
    const int b_k  = tid >> 5;   // 0..7 (+8)
    const int b_c4 = tid & 31;   // float4 col

    __syncthreads();

    float4 aReg[2], bReg[2];
    // prefetch chunk 0 (s = 0, i0 = 0)
    {
#pragma unroll
        for (int it = 0; it < 2; it++){
            int r = a_r + 64 * it;
            float4 v = *reinterpret_cast<const float4*>(&X[(size_t)(m0 + r) * DIN + a_c4 * 4]);
            float bs = sbasis[r * 12 + 0];
            v.x *= bs; v.y *= bs; v.z *= bs; v.w *= bs;
            aReg[it] = v;
        }
#pragma unroll
        for (int it = 0; it < 2; it++){
            int k = b_k + 8 * it;
            bReg[it] = *reinterpret_cast<const float4*>(&W[(size_t)k * 256 + n0 + b_c4 * 4]);
        }
    }

    const int row0 = (tid >> 4) * 4;   // 0..28, + 64 for upper half
    const int col0 = (tid & 15) * 4;   // 0..60, + 64 for right half
    float acc[8][8];
#pragma unroll
    for (int i = 0; i < 8; i++)
#pragma unroll
        for (int j = 0; j < 8; j++) acc[i][j] = 0.0f;

    for (int ck = 0; ck < NCK; ck++){
        // commit prefetched regs to smem
#pragma unroll
        for (int it = 0; it < 2; it++){
            int r = a_r + 64 * it;
            float4 v = aReg[it];
            As[(a_c4 * 4 + 0) * ASTR + r] = v.x;
            As[(a_c4 * 4 + 1) * ASTR + r] = v.y;
            As[(a_c4 * 4 + 2) * ASTR + r] = v.z;
            As[(a_c4 * 4 + 3) * ASTR + r] = v.w;
        }
#pragma unroll
        for (int it = 0; it < 2; it++){
            int k = b_k + 8 * it;
            *reinterpret_cast<float4*>(&Bs[k * 128 + b_c4 * 4]) = bReg[it];
        }
        __syncthreads();

        // prefetch next chunk (global latency overlapped with compute below)
        if (ck + 1 < NCK){
            const int kc = ck + 1;
            const int s  = kc >> 4;            // 16 chunks of 16 per s-slab
            const int i0 = (kc & 15) * BK;
#pragma unroll
            for (int it = 0; it < 2; it++){
                int r = a_r + 64 * it;
                float4 v = *reinterpret_cast<const float4*>(&X[(size_t)(m0 + r) * DIN + i0 + a_c4 * 4]);
                float bs = sbasis[r * 12 + s];
                v.x *= bs; v.y *= bs; v.z *= bs; v.w *= bs;
                aReg[it] = v;
            }
            const size_t kbase = (size_t)kc * BK;
#pragma unroll
            for (int it = 0; it < 2; it++){
                int k = b_k + 8 * it;
                bReg[it] = *reinterpret_cast<const float4*>(&W[(kbase + k) * 256 + n0 + b_c4 * 4]);
            }
        }

        // 8x8 microtile FFMA
#pragma unroll
        for (int k = 0; k < BK; k++){
            float a[8], b[8];
            float4 v;
            v = *reinterpret_cast<const float4*>(&As[k * ASTR + row0]);
            a[0] = v.x; a[1] = v.y; a[2] = v.z; a[3] = v.w;
            v = *reinterpret_cast<const float4*>(&As[k * ASTR + row0 + 64]);
            a[4] = v.x; a[5] = v.y; a[6] = v.z; a[7] = v.w;
            v = *reinterpret_cast<const float4*>(&Bs[k * 128 + col0]);
            b[0] = v.x; b[1] = v.y; b[2] = v.z; b[3] = v.w;
            v = *reinterpret_cast<const float4*>(&Bs[k * 128 + col0 + 64]);
            b[4] = v.x; b[5] = v.y; b[6] = v.z; b[7] = v.w;
#pragma unroll
            for (int i = 0; i < 8; i++)
#pragma unroll
                for (int j = 0; j < 8; j++)
                    acc[i][j] = fmaf(a[i], b[j], acc[i][j]);
        }
        __syncthreads();
    }

    // epilogue: + basis @ bias, optional relu
#pragma unroll
    for (int ii = 0; ii < 8; ii++){
        const int r = (ii < 4) ? (row0 + ii) : (row0 + 64 + ii - 4);
        float bb[12];
#pragma unroll
        for (int s = 0; s < 12; s++) bb[s] = sbasis[r * 12 + s];
        const size_t grow = (size_t)(m0 + r) * 256 + n0;
#pragma unroll
        for (int jj = 0; jj < 8; jj++){
            const int c = (jj < 4) ? (col0 + jj) : (col0 + 64 + jj - 4);
            float bias = 0.0f;
#pragma unroll
            for (int s = 0; s < 12; s++) bias = fmaf(bb[s], sbias[s * 128 + c], bias);
            float v = acc[ii][jj] + bias;
            if (RELU) v = fmaxf(v, 0.0f);
            Y[grow + c] = v;
        }
    }
}

// Final layer (out_dim = 1): out[b] = sum_i x[b,i] * (sum_s basis[b,s]*W2[s,i]) + basis·b2
__global__ void head_kernel(const float* __restrict__ T, const float* __restrict__ X,
                            const float* __restrict__ W2, const float* __restrict__ b2,
                            float* __restrict__ out)
{
    const int warp = threadIdx.x >> 5;
    const int lane = threadIdx.x & 31;
    const int row  = blockIdx.x * 8 + warp;

    float bb[12];
    basis_eval(T[row], bb);

    float acc = 0.0f;
#pragma unroll
    for (int ii = 0; ii < 8; ii++){
        const int i = lane + 32 * ii;
        float w = 0.0f;
#pragma unroll
        for (int s = 0; s < 12; s++) w = fmaf(bb[s], W2[s * 256 + i], w);
        acc = fmaf(X[(size_t)row * 256 + i], w, acc);
    }
#pragma unroll
    for (int off = 16; off; off >>= 1)
        acc += __shfl_xor_sync(0xffffffffu, acc, off);

    if (lane == 0){
        float bias = 0.0f;
#pragma unroll
        for (int s = 0; s < 12; s++) bias = fmaf(bb[s], b2[s], bias);
        out[row] = acc + bias;
    }
}

extern "C" void kernel_launch(void* const* d_in, const int* in_sizes, int n_in,
                              void* d_out, int out_size)
{
    const float* T  = (const float*)d_in[0];
    const float* X  = (const float*)d_in[1];
    const float* W0 = (const float*)d_in[2];
    const float* b0 = (const float*)d_in[3];
    const float* W1 = (const float*)d_in[4];
    const float* b1 = (const float*)d_in[5];
    const float* W2 = (const float*)d_in[6];
    const float* b2 = (const float*)d_in[7];
    float* out = (float*)d_out;

    float *buf0 = nullptr, *buf1 = nullptr;
    cudaGetSymbolAddress((void**)&buf0, g_buf0);
    cudaGetSymbolAddress((void**)&buf1, g_buf1);

    dim3 grid(2, 256);   // (N/128, B/128)
    vc_gemm<true><<<grid, 256>>>(T, X,    W0, b0, buf0);
    vc_gemm<true><<<grid, 256>>>(T, buf0, W1, b1, buf1);
    head_kernel<<<B_SZ / 8, 256>>>(T, buf1, W2, b2, out);
}

// round 4
// speedup vs baseline: 6.5796x; 6.5796x over previous
#include <cuda_runtime.h>
#include <cuda_bf16.h>
#include <math.h>
#include <stdint.h>

#define NROWS 32768
#define NBINS 9
#define MAXTILES 272
#define ASTR 40          /* bf16 row stride in smem tiles */

__device__ float g_buf0[(size_t)NROWS * 256];
__device__ float g_buf1[(size_t)NROWS * 256];
__device__ __nv_bfloat16 g_WpHi0[(size_t)NBINS * 256 * 1024];
__device__ __nv_bfloat16 g_WpLo0[(size_t)NBINS * 256 * 1024];
__device__ __nv_bfloat16 g_WpHi1[(size_t)NBINS * 256 * 1024];
__device__ __nv_bfloat16 g_WpLo1[(size_t)NBINS * 256 * 1024];
__device__ float g_Pb0[NBINS * 4 * 256];
__device__ float g_Pb1[NBINS * 4 * 256];
__device__ int   g_perm[NROWS];
__device__ float g_tp[NROWS];
__device__ int   g_binstart[NBINS + 1];
__device__ int   g_tilebin[MAXTILES];
__device__ int   g_tilem0[MAXTILES];
__device__ int   g_ntiles;

__constant__ float c_knots[8] = {
    1.0f/9.0f, 2.0f/9.0f, 3.0f/9.0f, 4.0f/9.0f,
    5.0f/9.0f, 6.0f/9.0f, 7.0f/9.0f, 8.0f/9.0f
};

__device__ __forceinline__ void basis_eval(float t, float* bb){
    bb[0] = 1.0f; bb[1] = t; bb[2] = t*t; bb[3] = bb[2]*t;
#pragma unroll
    for (int j = 0; j < 8; j++){
        float d = fmaxf(t - c_knots[j], 0.0f);
        bb[4+j] = d*d*d;
    }
}

__device__ __forceinline__ void mma_bf16(float* c, const uint32_t* a, uint32_t b0, uint32_t b1){
    asm volatile(
        "mma.sync.aligned.m16n8k16.row.col.f32.bf16.bf16.f32 "
        "{%0,%1,%2,%3},{%4,%5,%6,%7},{%8,%9},{%0,%1,%2,%3};"
        : "+f"(c[0]), "+f"(c[1]), "+f"(c[2]), "+f"(c[3])
        : "r"(a[0]), "r"(a[1]), "r"(a[2]), "r"(a[3]), "r"(b0), "r"(b1));
}

// ---------------- bin setup: histogram -> scan -> tiles -> scatter ----------------
__global__ void setup_bins(const float* __restrict__ T){
    __shared__ int scnt[NBINS], scur[NBINS];
    const int tid = threadIdx.x, lane = tid & 31;
    if (tid < NBINS) scnt[tid] = 0;
    __syncthreads();
    for (int i = tid; i < NROWS; i += 1024){
        int b = (int)(T[i] * 9.0f); b = b < 0 ? 0 : (b > 8 ? 8 : b);
        unsigned m = __match_any_sync(0xffffffffu, b);
        if (lane == __ffs(m) - 1) atomicAdd(&scnt[b], __popc(m));
    }
    __syncthreads();
    if (tid == 0){
        int off = 0, nt = 0;
        for (int b = 0; b < NBINS; b++){
            g_binstart[b] = off;
            scur[b] = off;
            for (int ms = 0; ms < scnt[b]; ms += 128){
                g_tilebin[nt] = b; g_tilem0[nt] = off + ms; nt++;
            }
            off += scnt[b];
        }
        g_binstart[NBINS] = off;
        g_ntiles = nt;
    }
    __syncthreads();
    for (int i = tid; i < NROWS; i += 1024){
        float t = T[i];
        int b = (int)(t * 9.0f); b = b < 0 ? 0 : (b > 8 ? 8 : b);
        unsigned m = __match_any_sync(0xffffffffu, b);
        int ldr = __ffs(m) - 1;
        int pre = __popc(m & ((1u << lane) - 1u));
        int base = 0;
        if (lane == ldr) base = atomicAdd(&scur[b], __popc(m));
        base = __shfl_sync(0xffffffffu, base, ldr);
        g_perm[base + pre] = i;
        g_tp[base + pre] = t;
    }
}

// ---------------- prep: W(3072x256) -> per-bin poly weights [bin][o][j*256+i], split bf16 ----------------
__global__ void prep_w(const float* __restrict__ W,
                       __nv_bfloat16* __restrict__ Hi, __nv_bfloat16* __restrict__ Lo){
    const int i = threadIdx.x, o = blockIdx.x;
    float w[12];
#pragma unroll
    for (int s = 0; s < 12; s++) w[s] = W[(size_t)(s*256 + i)*256 + o];
    float p[4] = {w[0], w[1], w[2], w[3]};
    for (int bin = 0; bin < NBINS; bin++){
        if (bin >= 1){
            float k = (float)bin / 9.0f, ww = w[3 + bin];
            p[3] += ww; p[2] -= 3.0f*k*ww; p[1] += 3.0f*k*k*ww; p[0] -= k*k*k*ww;
        }
#pragma unroll
        for (int j = 0; j < 4; j++){
            size_t idx = ((size_t)bin*256 + o)*1024 + j*256 + i;
            __nv_bfloat16 h = __float2bfloat16(p[j]);
            Hi[idx] = h;
            Lo[idx] = __float2bfloat16(p[j] - __bfloat162float(h));
        }
    }
}

__global__ void prep_b(const float* __restrict__ Bv, float* __restrict__ Pb){
    const int o = threadIdx.x;
    float w[12];
#pragma unroll
    for (int s = 0; s < 12; s++) w[s] = Bv[s*256 + o];
    float p[4] = {w[0], w[1], w[2], w[3]};
    for (int bin = 0; bin < NBINS; bin++){
        if (bin >= 1){
            float k = (float)bin / 9.0f, ww = w[3 + bin];
            p[3] += ww; p[2] -= 3.0f*k*ww; p[1] += 3.0f*k*k*ww; p[0] -= k*k*k*ww;
        }
#pragma unroll
        for (int j = 0; j < 4; j++) Pb[(bin*4 + j)*256 + o] = p[j];
    }
}

// ---------------- GEMM: Y[pos,n] = sum_k (t^j x_i) P[bin,k,n] + bias, split-bf16 mma ----------------
template<bool GATHER, bool RELU>
__global__ void __launch_bounds__(256) vc_gemm(
    const float* __restrict__ Xsrc,
    const __nv_bfloat16* __restrict__ WHi, const __nv_bfloat16* __restrict__ WLo,
    const float* __restrict__ Pb, float* __restrict__ Y)
{
    const int tile = blockIdx.x;
    if (tile >= g_ntiles) return;
    __shared__ __nv_bfloat16 Ahi[128*ASTR], Alo[128*ASTR];
    __shared__ __nv_bfloat16 Bhi[128*ASTR], Blo[128*ASTR];
    __shared__ float spw[128][4];
    __shared__ float pbs[4][128];

    const int tid = threadIdx.x, wid = tid >> 5, lane = tid & 31;
    const int bin = g_tilebin[tile];
    const int m0  = g_tilem0[tile];
    const int rows = min(128, g_binstart[bin + 1] - m0);
    const int n0 = blockIdx.y * 128;

    if (tid < 128){
        float t = (tid < rows) ? g_tp[m0 + tid] : 0.0f;
        float e = (tid < rows) ? 1.0f : 0.0f;
        spw[tid][0] = e; spw[tid][1] = e*t; spw[tid][2] = e*t*t; spw[tid][3] = e*t*t*t;
    }
#pragma unroll
    for (int q = 0; q < 2; q++){
        int idx = q*256 + tid;
        pbs[idx >> 7][idx & 127] = Pb[(bin*4 + (idx >> 7))*256 + n0 + (idx & 127)];
    }

    // A-build mapping: thread -> row r, 16-col half h
    const int r = tid >> 1, h = tid & 1;
    const int rs = min(r, rows - 1);
    const float* xrow = Xsrc + (size_t)(GATHER ? g_perm[m0 + rs] : (m0 + rs)) * 256 + h*16;
    // B-load mapping
    const size_t wbase = (size_t)bin * 256 * 1024;

    __syncthreads();

    float4 xr[4];
    uint4 bh[2], bl[2];
    // prefetch slab 0
    {
        const int i0 = 0;
#pragma unroll
        for (int q = 0; q < 4; q++) xr[q] = *(const float4*)(xrow + i0 + q*4);
#pragma unroll
        for (int it = 0; it < 2; it++){
            int idx = it*256 + tid, o = idx >> 2, q = idx & 3;
            const __nv_bfloat16* gp = WHi + wbase + (size_t)(n0 + o)*1024 + i0 + q*8;
            bh[it] = *(const uint4*)gp;
            bl[it] = *(const uint4*)(WLo + wbase + (size_t)(n0 + o)*1024 + i0 + q*8);
        }
    }

    const int wm = (wid >> 1) * 32, wn = (wid & 1) * 64;
    const int lr = lane >> 2, lk = lane & 3;
    float acc[2][8][4];
#pragma unroll
    for (int a = 0; a < 2; a++)
#pragma unroll
        for (int b = 0; b < 8; b++)
#pragma unroll
            for (int c = 0; c < 4; c++) acc[a][b][c] = 0.0f;

    for (int s = 0; s < 32; s++){
        const int j = s >> 3;
        __syncthreads();
        // commit A (t^j * x, split) and B to smem
        {
            const float pw = spw[r][j];
#pragma unroll
            for (int p = 0; p < 2; p++){
                uint32_t hi4[4], lo4[4];
#pragma unroll
                for (int e = 0; e < 4; e++){
                    float v0 = pw * ((const float*)&xr[p*2 + (e>>1)])[(e&1)*2 + 0];
                    float v1 = pw * ((const float*)&xr[p*2 + (e>>1)])[(e&1)*2 + 1];
                    __nv_bfloat162 h2 = __floats2bfloat162_rn(v0, v1);
                    hi4[e] = *(uint32_t*)&h2;
                    __nv_bfloat162 l2 = __floats2bfloat162_rn(
                        v0 - __bfloat162float(h2.x), v1 - __bfloat162float(h2.y));
                    lo4[e] = *(uint32_t*)&l2;
                }
                int ofs = r*(ASTR*2) + h*32 + p*16;
                *(uint4*)((char*)Ahi + ofs) = make_uint4(hi4[0], hi4[1], hi4[2], hi4[3]);
                *(uint4*)((char*)Alo + ofs) = make_uint4(lo4[0], lo4[1], lo4[2], lo4[3]);
            }
#pragma unroll
            for (int it = 0; it < 2; it++){
                int idx = it*256 + tid, o = idx >> 2, q = idx & 3;
                int ofs = o*(ASTR*2) + q*16;
                *(uint4*)((char*)Bhi + ofs) = bh[it];
                *(uint4*)((char*)Blo + ofs) = bl[it];
            }
        }
        // prefetch slab s+1
        if (s < 31){
            const int sn = s + 1, i0 = (sn & 7) * 32;
#pragma unroll
            for (int q = 0; q < 4; q++) xr[q] = *(const float4*)(xrow + i0 + q*4);
            const size_t jb = wbase + (size_t)(sn >> 3) * 256 + i0;
#pragma unroll
            for (int it = 0; it < 2; it++){
                int idx = it*256 + tid, o = idx >> 2, q = idx & 3;
                bh[it] = *(const uint4*)(WHi + jb + (size_t)(n0 + o)*1024 - (size_t)(sn>>3)*256 + (size_t)(sn>>3)*256 + q*8);
                bl[it] = *(const uint4*)(WLo + wbase + (size_t)(n0 + o)*1024 + (sn>>3)*256 + i0 + q*8);
            }
            // fix bh to the simple form (identical address math as bl)
#pragma unroll
            for (int it = 0; it < 2; it++){
                int idx = it*256 + tid, o = idx >> 2, q = idx & 3;
                bh[it] = *(const uint4*)(WHi + wbase + (size_t)(n0 + o)*1024 + (sn>>3)*256 + i0 + q*8);
            }
        }
        __syncthreads();
        // MMA on slab s
#pragma unroll
        for (int kk = 0; kk < 2; kk++){
            uint32_t ah[2][4], al[2][4];
#pragma unroll
            for (int mt = 0; mt < 2; mt++){
                int row = wm + mt*16 + lr;
                int kb = (kk*16 + lk*2) * 2;       // byte offset of k
                ah[mt][0] = *(uint32_t*)((char*)Ahi + row*(ASTR*2) + kb);
                ah[mt][1] = *(uint32_t*)((char*)Ahi + (row+8)*(ASTR*2) + kb);
                ah[mt][2] = *(uint32_t*)((char*)Ahi + row*(ASTR*2) + kb + 16);
                ah[mt][3] = *(uint32_t*)((char*)Ahi + (row+8)*(ASTR*2) + kb + 16);
                al[mt][0] = *(uint32_t*)((char*)Alo + row*(ASTR*2) + kb);
                al[mt][1] = *(uint32_t*)((char*)Alo + (row+8)*(ASTR*2) + kb);
                al[mt][2] = *(uint32_t*)((char*)Alo + row*(ASTR*2) + kb + 16);
                al[mt][3] = *(uint32_t*)((char*)Alo + (row+8)*(ASTR*2) + kb + 16);
            }
#pragma unroll
            for (int nt = 0; nt < 8; nt++){
                int col = wn + nt*8 + lr;
                int kb = (kk*16 + lk*2) * 2;
                uint32_t b0 = *(uint32_t*)((char*)Bhi + col*(ASTR*2) + kb);
                uint32_t b1 = *(uint32_t*)((char*)Bhi + col*(ASTR*2) + kb + 16);
                uint32_t c0 = *(uint32_t*)((char*)Blo + col*(ASTR*2) + kb);
                uint32_t c1 = *(uint32_t*)((char*)Blo + col*(ASTR*2) + kb + 16);
#pragma unroll
                for (int mt = 0; mt < 2; mt++){
                    mma_bf16(acc[mt][nt], ah[mt], b0, b1);
                    mma_bf16(acc[mt][nt], ah[mt], c0, c1);
                    mma_bf16(acc[mt][nt], al[mt], b0, b1);
                }
            }
        }
    }

    // epilogue: + poly bias, relu, store (permuted row space)
#pragma unroll
    for (int mt = 0; mt < 2; mt++){
#pragma unroll
        for (int half = 0; half < 2; half++){
            int rr = wm + mt*16 + lr + half*8;
            if (rr >= rows) continue;
            float pw0 = spw[rr][0], pw1 = spw[rr][1], pw2 = spw[rr][2], pw3 = spw[rr][3];
            float* yp = Y + (size_t)(m0 + rr) * 256 + n0;
#pragma unroll
            for (int nt = 0; nt < 8; nt++){
                int col = wn + nt*8 + lk*2;
                float b0 = pw0*pbs[0][col]   + pw1*pbs[1][col]   + pw2*pbs[2][col]   + pw3*pbs[3][col];
                float b1 = pw0*pbs[0][col+1] + pw1*pbs[1][col+1] + pw2*pbs[2][col+1] + pw3*pbs[3][col+1];
                float v0 = acc[mt][nt][half*2 + 0] + b0;
                float v1 = acc[mt][nt][half*2 + 1] + b1;
                if (RELU){ v0 = fmaxf(v0, 0.0f); v1 = fmaxf(v1, 0.0f); }
                *(float2*)(yp + col) = make_float2(v0, v1);
            }
        }
    }
}

// ---------------- head: out[perm[pos]] = x_pos · (Σ_s φ_s W2_s) + φ·b2 ----------------
__global__ void head_kernel(const float* __restrict__ X,
                            const float* __restrict__ W2, const float* __restrict__ b2,
                            float* __restrict__ out)
{
    const int warp = threadIdx.x >> 5, lane = threadIdx.x & 31;
    const int pos = blockIdx.x * 8 + warp;
    float bb[12];
    basis_eval(g_tp[pos], bb);
    float acc = 0.0f;
#pragma unroll
    for (int ii = 0; ii < 8; ii++){
        const int i = lane + 32*ii;
        float w = 0.0f;
#pragma unroll
        for (int s = 0; s < 12; s++) w = fmaf(bb[s], W2[s*256 + i], w);
        acc = fmaf(X[(size_t)pos*256 + i], w, acc);
    }
#pragma unroll
    for (int off = 16; off; off >>= 1) acc += __shfl_xor_sync(0xffffffffu, acc, off);
    if (lane == 0){
        float bias = 0.0f;
#pragma unroll
        for (int s = 0; s < 12; s++) bias = fmaf(bb[s], b2[s], bias);
        out[g_perm[pos]] = acc + bias;
    }
}

extern "C" void kernel_launch(void* const* d_in, const int* in_sizes, int n_in,
                              void* d_out, int out_size)
{
    const float* T  = (const float*)d_in[0];
    const float* X  = (const float*)d_in[1];
    const float* W0 = (const float*)d_in[2];
    const float* b0 = (const float*)d_in[3];
    const float* W1 = (const float*)d_in[4];
    const float* b1 = (const float*)d_in[5];
    const float* W2 = (const float*)d_in[6];
    const float* b2 = (const float*)d_in[7];
    float* out = (float*)d_out;

    float *buf0, *buf1, *pb0, *pb1;
    __nv_bfloat16 *wh0, *wl0, *wh1, *wl1;
    cudaGetSymbolAddress((void**)&buf0, g_buf0);
    cudaGetSymbolAddress((void**)&buf1, g_buf1);
    cudaGetSymbolAddress((void**)&wh0, g_WpHi0);
    cudaGetSymbolAddress((void**)&wl0, g_WpLo0);
    cudaGetSymbolAddress((void**)&wh1, g_WpHi1);
    cudaGetSymbolAddress((void**)&wl1, g_WpLo1);
    cudaGetSymbolAddress((void**)&pb0, g_Pb0);
    cudaGetSymbolAddress((void**)&pb1, g_Pb1);

    setup_bins<<<1, 1024>>>(T);
    prep_w<<<256, 256>>>(W0, wh0, wl0);
    prep_w<<<256, 256>>>(W1, wh1, wl1);
    prep_b<<<1, 256>>>(b0, pb0);
    prep_b<<<1, 256>>>(b1, pb1);

    dim3 grid(MAXTILES, 2);
    vc_gemm<true,  true><<<grid, 256>>>(X,    wh0, wl0, pb0, buf0);
    vc_gemm<false, true><<<grid, 256>>>(buf0, wh1, wl1, pb1, buf1);
    head_kernel<<<NROWS / 8, 256>>>(buf1, W2, b2, out);
}

// round 5
// speedup vs baseline: 7.8734x; 1.1966x over previous
#include <cuda_runtime.h>
#include <cuda_bf16.h>
#include <cuda_fp16.h>
#include <math.h>
#include <stdint.h>

#define NROWS 32768
#define NBINS 9
#define MAXTILES 272
#define ASTR 40          /* 16-bit elems per smem row (80 B), conflict-free */

__device__ float g_buf0[(size_t)NROWS * 256];
__device__ float g_buf1[(size_t)NROWS * 256];
__device__ __half         g_WpHi0[(size_t)NBINS * 256 * 1024];
__device__ __nv_bfloat16  g_WpLo0[(size_t)NBINS * 256 * 1024];
__device__ __half         g_WpHi1[(size_t)NBINS * 256 * 1024];
__device__ __nv_bfloat16  g_WpLo1[(size_t)NBINS * 256 * 1024];
__device__ float g_Pb0[NBINS * 4 * 256];
__device__ float g_Pb1[NBINS * 4 * 256];
__device__ int   g_perm[NROWS];
__device__ float g_tp[NROWS];
__device__ int   g_binstart[NBINS + 1];
__device__ int   g_bincnt[NBINS];
__device__ int   g_cur[NBINS];
__device__ int   g_tilebin[MAXTILES];
__device__ int   g_tilem0[MAXTILES];
__device__ int   g_ntiles;

__constant__ float c_knots[8] = {
    1.0f/9.0f, 2.0f/9.0f, 3.0f/9.0f, 4.0f/9.0f,
    5.0f/9.0f, 6.0f/9.0f, 7.0f/9.0f, 8.0f/9.0f
};

__device__ __forceinline__ void basis_eval(float t, float* bb){
    bb[0] = 1.0f; bb[1] = t; bb[2] = t*t; bb[3] = bb[2]*t;
#pragma unroll
    for (int j = 0; j < 8; j++){
        float d = fmaxf(t - c_knots[j], 0.0f);
        bb[4+j] = d*d*d;
    }
}

__device__ __forceinline__ void mma_f16(float* c, const uint32_t* a, uint32_t b0, uint32_t b1){
    asm volatile(
        "mma.sync.aligned.m16n8k16.row.col.f32.f16.f16.f32 "
        "{%0,%1,%2,%3},{%4,%5,%6,%7},{%8,%9},{%0,%1,%2,%3};"
        : "+f"(c[0]), "+f"(c[1]), "+f"(c[2]), "+f"(c[3])
        : "r"(a[0]), "r"(a[1]), "r"(a[2]), "r"(a[3]), "r"(b0), "r"(b1));
}
__device__ __forceinline__ void mma_bf16(float* c, const uint32_t* a, uint32_t b0, uint32_t b1){
    asm volatile(
        "mma.sync.aligned.m16n8k16.row.col.f32.bf16.bf16.f32 "
        "{%0,%1,%2,%3},{%4,%5,%6,%7},{%8,%9},{%0,%1,%2,%3};"
        : "+f"(c[0]), "+f"(c[1]), "+f"(c[2]), "+f"(c[3])
        : "r"(a[0]), "r"(a[1]), "r"(a[2]), "r"(a[3]), "r"(b0), "r"(b1));
}

// ---------------- parallel bin setup ----------------
__global__ void bins_zero(){
    if (threadIdx.x < NBINS) g_bincnt[threadIdx.x] = 0;
}
__global__ void bins_hist(const float* __restrict__ T){
    const int tid = blockIdx.x * blockDim.x + threadIdx.x;
    const int lane = threadIdx.x & 31;
    for (int i = tid; i < NROWS; i += gridDim.x * blockDim.x){
        int b = (int)(T[i] * 9.0f); b = b < 0 ? 0 : (b > 8 ? 8 : b);
        unsigned m = __match_any_sync(__activemask(), b);
        if (lane == __ffs(m) - 1) atomicAdd(&g_bincnt[b], __popc(m));
    }
}
__global__ void bins_scan(){
    if (threadIdx.x == 0){
        int off = 0, nt = 0;
        for (int b = 0; b < NBINS; b++){
            g_binstart[b] = off;
            g_cur[b] = off;
            int cnt = g_bincnt[b];
            for (int ms = 0; ms < cnt; ms += 128){
                g_tilebin[nt] = b; g_tilem0[nt] = off + ms; nt++;
            }
            off += cnt;
        }
        g_binstart[NBINS] = off;
        g_ntiles = nt;
    }
}
__global__ void bins_scatter(const float* __restrict__ T){
    const int tid = blockIdx.x * blockDim.x + threadIdx.x;
    const int lane = threadIdx.x & 31;
    for (int i = tid; i < NROWS; i += gridDim.x * blockDim.x){
        float t = T[i];
        int b = (int)(t * 9.0f); b = b < 0 ? 0 : (b > 8 ? 8 : b);
        unsigned msk = __activemask();
        unsigned m = __match_any_sync(msk, b);
        int ldr = __ffs(m) - 1;
        int pre = __popc(m & ((1u << lane) - 1u));
        int base = 0;
        if (lane == ldr) base = atomicAdd(&g_cur[b], __popc(m));
        base = __shfl_sync(msk, base, ldr);
        g_perm[base + pre] = i;
        g_tp[base + pre] = t;
    }
}

// ---------------- prep: W(3072x256) -> per-bin poly weights [bin][o][j*256+i] ----------------
// Hi = fp16(P), Lo = bf16(P - Hi)   (Lo in bf16: residual magnitudes would be fp16-subnormal)
__global__ void prep_w(const float* __restrict__ W,
                       __half* __restrict__ Hi, __nv_bfloat16* __restrict__ Lo){
    const int i = threadIdx.x, o = blockIdx.x;
    float w[12];
#pragma unroll
    for (int s = 0; s < 12; s++) w[s] = W[(size_t)(s*256 + i)*256 + o];
    float p[4] = {w[0], w[1], w[2], w[3]};
    for (int bin = 0; bin < NBINS; bin++){
        if (bin >= 1){
            float k = (float)bin / 9.0f, ww = w[3 + bin];
            p[3] += ww; p[2] -= 3.0f*k*ww; p[1] += 3.0f*k*k*ww; p[0] -= k*k*k*ww;
        }
#pragma unroll
        for (int j = 0; j < 4; j++){
            size_t idx = ((size_t)bin*256 + o)*1024 + j*256 + i;
            __half h = __float2half_rn(p[j]);
            Hi[idx] = h;
            Lo[idx] = __float2bfloat16(p[j] - __half2float(h));
        }
    }
}

__global__ void prep_b(const float* __restrict__ Bv, float* __restrict__ Pb){
    const int o = threadIdx.x;
    float w[12];
#pragma unroll
    for (int s = 0; s < 12; s++) w[s] = Bv[s*256 + o];
    float p[4] = {w[0], w[1], w[2], w[3]};
    for (int bin = 0; bin < NBINS; bin++){
        if (bin >= 1){
            float k = (float)bin / 9.0f, ww = w[3 + bin];
            p[3] += ww; p[2] -= 3.0f*k*ww; p[1] += 3.0f*k*k*ww; p[0] -= k*k*k*ww;
        }
#pragma unroll
        for (int j = 0; j < 4; j++) Pb[(bin*4 + j)*256 + o] = p[j];
    }
}

// ---------------- GEMM: Y[pos,n] = sum_k (t^j x_i) P[bin,k,n] + bias ----------------
// 2-pass: A_fp16 * Bhi_fp16  +  A_bf16 * Blo_bf16
template<bool GATHER, bool RELU>
__global__ void __launch_bounds__(256) vc_gemm(
    const float* __restrict__ Xsrc,
    const __half* __restrict__ WHi, const __nv_bfloat16* __restrict__ WLo,
    const float* __restrict__ Pb, float* __restrict__ Y)
{
    const int tile = blockIdx.x;
    if (tile >= g_ntiles) return;
    __shared__ __half        Ah[128*ASTR];
    __shared__ __nv_bfloat16 Ab[128*ASTR];
    __shared__ __half        Bh[128*ASTR];
    __shared__ __nv_bfloat16 Bl[128*ASTR];
    __shared__ float spw[128][4];
    __shared__ float pbs[4][128];

    const int tid = threadIdx.x, wid = tid >> 5, lane = tid & 31;
    const int bin = g_tilebin[tile];
    const int m0  = g_tilem0[tile];
    const int rows = min(128, g_binstart[bin + 1] - m0);
    const int n0 = blockIdx.y * 128;

    if (tid < 128){
        float t = (tid < rows) ? g_tp[m0 + tid] : 0.0f;
        float e = (tid < rows) ? 1.0f : 0.0f;
        spw[tid][0] = e; spw[tid][1] = e*t; spw[tid][2] = e*t*t; spw[tid][3] = e*t*t*t;
    }
#pragma unroll
    for (int q = 0; q < 2; q++){
        int idx = q*256 + tid;
        pbs[idx >> 7][idx & 127] = Pb[(bin*4 + (idx >> 7))*256 + n0 + (idx & 127)];
    }

    const int r = tid >> 1, h = tid & 1;
    const int rs = min(r, rows - 1);
    const float* xrow = Xsrc + (size_t)(GATHER ? g_perm[m0 + rs] : (m0 + rs)) * 256 + h*16;
    const size_t wbase = (size_t)bin * 256 * 1024;

    __syncthreads();

    float4 xr[4];
    uint4 bh[2], bl[2];
    {   // prefetch slab 0
#pragma unroll
        for (int q = 0; q < 4; q++) xr[q] = *(const float4*)(xrow + q*4);
#pragma unroll
        for (int it = 0; it < 2; it++){
            int idx = it*256 + tid, o = idx >> 2, q = idx & 3;
            bh[it] = *(const uint4*)(WHi + wbase + (size_t)(n0 + o)*1024 + q*8);
            bl[it] = *(const uint4*)(WLo + wbase + (size_t)(n0 + o)*1024 + q*8);
        }
    }

    const int wm = (wid >> 1) * 32, wn = (wid & 1) * 64;
    const int lr = lane >> 2, lk = lane & 3;
    float acc[2][8][4];
#pragma unroll
    for (int a = 0; a < 2; a++)
#pragma unroll
        for (int b = 0; b < 8; b++)
#pragma unroll
            for (int c = 0; c < 4; c++) acc[a][b][c] = 0.0f;

    for (int s = 0; s < 32; s++){
        const int j = s >> 3;
        __syncthreads();
        // commit A (t^j * x, fp16 + bf16 views) and B to smem
        {
            const float pw = spw[r][j];
            const float* xe = (const float*)xr;
#pragma unroll
            for (int p = 0; p < 2; p++){
                uint32_t hf[4], bf[4];
#pragma unroll
                for (int e = 0; e < 4; e++){
                    float v0 = pw * xe[p*8 + e*2];
                    float v1 = pw * xe[p*8 + e*2 + 1];
                    __half2 h2 = __floats2half2_rn(v0, v1);
                    hf[e] = *(uint32_t*)&h2;
                    __nv_bfloat162 b2 = __floats2bfloat162_rn(v0, v1);
                    bf[e] = *(uint32_t*)&b2;
                }
                int ofs = r*(ASTR*2) + h*32 + p*16;
                *(uint4*)((char*)Ah + ofs) = make_uint4(hf[0], hf[1], hf[2], hf[3]);
                *(uint4*)((char*)Ab + ofs) = make_uint4(bf[0], bf[1], bf[2], bf[3]);
            }
#pragma unroll
            for (int it = 0; it < 2; it++){
                int idx = it*256 + tid, o = idx >> 2, q = idx & 3;
                int ofs = o*(ASTR*2) + q*16;
                *(uint4*)((char*)Bh + ofs) = bh[it];
                *(uint4*)((char*)Bl + ofs) = bl[it];
            }
        }
        // prefetch slab s+1
        if (s < 31){
            const int sn = s + 1, i0 = (sn & 7) * 32, jn = sn >> 3;
#pragma unroll
            for (int q = 0; q < 4; q++) xr[q] = *(const float4*)(xrow + i0 + q*4);
#pragma unroll
            for (int it = 0; it < 2; it++){
                int idx = it*256 + tid, o = idx >> 2, q = idx & 3;
                size_t gofs = wbase + (size_t)(n0 + o)*1024 + jn*256 + i0 + q*8;
                bh[it] = *(const uint4*)(WHi + gofs);
                bl[it] = *(const uint4*)(WLo + gofs);
            }
        }
        __syncthreads();
        // MMA on slab s
#pragma unroll
        for (int kk = 0; kk < 2; kk++){
            const int kb = (kk*16 + lk*2) * 2;
            uint32_t ah[2][4], ab[2][4];
#pragma unroll
            for (int mt = 0; mt < 2; mt++){
                int row = wm + mt*16 + lr;
                ah[mt][0] = *(uint32_t*)((char*)Ah + row*(ASTR*2) + kb);
                ah[mt][1] = *(uint32_t*)((char*)Ah + (row+8)*(ASTR*2) + kb);
                ah[mt][2] = *(uint32_t*)((char*)Ah + row*(ASTR*2) + kb + 16);
                ah[mt][3] = *(uint32_t*)((char*)Ah + (row+8)*(ASTR*2) + kb + 16);
                ab[mt][0] = *(uint32_t*)((char*)Ab + row*(ASTR*2) + kb);
                ab[mt][1] = *(uint32_t*)((char*)Ab + (row+8)*(ASTR*2) + kb);
                ab[mt][2] = *(uint32_t*)((char*)Ab + row*(ASTR*2) + kb + 16);
                ab[mt][3] = *(uint32_t*)((char*)Ab + (row+8)*(ASTR*2) + kb + 16);
            }
#pragma unroll
            for (int nt = 0; nt < 8; nt++){
                int col = wn + nt*8 + lr;
                uint32_t b0 = *(uint32_t*)((char*)Bh + col*(ASTR*2) + kb);
                uint32_t b1 = *(uint32_t*)((char*)Bh + col*(ASTR*2) + kb + 16);
                uint32_t c0 = *(uint32_t*)((char*)Bl + col*(ASTR*2) + kb);
                uint32_t c1 = *(uint32_t*)((char*)Bl + col*(ASTR*2) + kb + 16);
#pragma unroll
                for (int mt = 0; mt < 2; mt++){
                    mma_f16(acc[mt][nt], ah[mt], b0, b1);
                    mma_bf16(acc[mt][nt], ab[mt], c0, c1);
                }
            }
        }
    }

    // epilogue: + poly bias, relu, store (permuted row space)
#pragma unroll
    for (int mt = 0; mt < 2; mt++){
#pragma unroll
        for (int half = 0; half < 2; half++){
            int rr = wm + mt*16 + lr + half*8;
            if (rr >= rows) continue;
            float pw0 = spw[rr][0], pw1 = spw[rr][1], pw2 = spw[rr][2], pw3 = spw[rr][3];
            float* yp = Y + (size_t)(m0 + rr) * 256 + n0;
#pragma unroll
            for (int nt = 0; nt < 8; nt++){
                int col = wn + nt*8 + lk*2;
                float b0 = pw0*pbs[0][col]   + pw1*pbs[1][col]   + pw2*pbs[2][col]   + pw3*pbs[3][col];
                float b1 = pw0*pbs[0][col+1] + pw1*pbs[1][col+1] + pw2*pbs[2][col+1] + pw3*pbs[3][col+1];
                float v0 = acc[mt][nt][half*2 + 0] + b0;
                float v1 = acc[mt][nt][half*2 + 1] + b1;
                if (RELU){ v0 = fmaxf(v0, 0.0f); v1 = fmaxf(v1, 0.0f); }
                *(float2*)(yp + col) = make_float2(v0, v1);
            }
        }
    }
}

// ---------------- head: out[perm[pos]] = x_pos · (Σ_s φ_s W2_s) + φ·b2 ----------------
__global__ void head_kernel(const float* __restrict__ X,
                            const float* __restrict__ W2, const float* __restrict__ b2,
                            float* __restrict__ out)
{
    const int warp = threadIdx.x >> 5, lane = threadIdx.x & 31;
    const int pos = blockIdx.x * 8 + warp;
    float bb[12];
    basis_eval(g_tp[pos], bb);
    float acc = 0.0f;
#pragma unroll
    for (int ii = 0; ii < 8; ii++){
        const int i = lane + 32*ii;
        float w = 0.0f;
#pragma unroll
        for (int s = 0; s < 12; s++) w = fmaf(bb[s], W2[s*256 + i], w);
        acc = fmaf(X[(size_t)pos*256 + i], w, acc);
    }
#pragma unroll
    for (int off = 16; off; off >>= 1) acc += __shfl_xor_sync(0xffffffffu, acc, off);
    if (lane == 0){
        float bias = 0.0f;
#pragma unroll
        for (int s = 0; s < 12; s++) bias = fmaf(bb[s], b2[s], bias);
        out[g_perm[pos]] = acc + bias;
    }
}

extern "C" void kernel_launch(void* const* d_in, const int* in_sizes, int n_in,
                              void* d_out, int out_size)
{
    const float* T  = (const float*)d_in[0];
    const float* X  = (const float*)d_in[1];
    const float* W0 = (const float*)d_in[2];
    const float* b0 = (const float*)d_in[3];
    const float* W1 = (const float*)d_in[4];
    const float* b1 = (const float*)d_in[5];
    const float* W2 = (const float*)d_in[6];
    const float* b2 = (const float*)d_in[7];
    float* out = (float*)d_out;

    float *buf0, *buf1, *pb0, *pb1;
    __half *wh0, *wh1;
    __nv_bfloat16 *wl0, *wl1;
    cudaGetSymbolAddress((void**)&buf0, g_buf0);
    cudaGetSymbolAddress((void**)&buf1, g_buf1);
    cudaGetSymbolAddress((void**)&wh0, g_WpHi0);
    cudaGetSymbolAddress((void**)&wl0, g_WpLo0);
    cudaGetSymbolAddress((void**)&wh1, g_WpHi1);
    cudaGetSymbolAddress((void**)&wl1, g_WpLo1);
    cudaGetSymbolAddress((void**)&pb0, g_Pb0);
    cudaGetSymbolAddress((void**)&pb1, g_Pb1);

    bins_zero<<<1, 32>>>();
    bins_hist<<<64, 512>>>(T);
    bins_scan<<<1, 32>>>();
    bins_scatter<<<64, 512>>>(T);

    prep_w<<<256, 256>>>(W0, wh0, wl0);
    prep_w<<<256, 256>>>(W1, wh1, wl1);
    prep_b<<<1, 256>>>(b0, pb0);
    prep_b<<<1, 256>>>(b1, pb1);

    dim3 grid(MAXTILES, 2);
    vc_gemm<true,  true><<<grid, 256>>>(X,    wh0, wl0, pb0, buf0);
    vc_gemm<false, true><<<grid, 256>>>(buf0, wh1, wl1, pb1, buf1);
    head_kernel<<<NROWS / 8, 256>>>(buf1, W2, b2, out);
}

// round 6
// speedup vs baseline: 14.2652x; 1.8118x over previous
#include <cuda_runtime.h>
#include <cuda_bf16.h>
#include <cuda_fp16.h>
#include <math.h>
#include <stdint.h>

#define NROWS 32768
#define NBINS 9
#define MAXTILES 272
#define ASTR 40          /* 16-bit elems per smem row (80 B) */

__device__ float g_buf0[(size_t)NROWS * 256];
__device__ float g_buf1[(size_t)NROWS * 256];
__device__ __half g_Wp0[(size_t)NBINS * 256 * 1024];
__device__ __half g_Wp1[(size_t)NBINS * 256 * 1024];
__device__ float g_Pb0[NBINS * 4 * 256];
__device__ float g_Pb1[NBINS * 4 * 256];
__device__ int   g_perm[NROWS];
__device__ float g_tp[NROWS];
__device__ int   g_binstart[NBINS + 1];
__device__ int   g_bincnt[NBINS];
__device__ int   g_cur[NBINS];
__device__ int   g_tilebin[MAXTILES];
__device__ int   g_tilem0[MAXTILES];
__device__ int   g_ntiles;

__constant__ float c_knots[8] = {
    1.0f/9.0f, 2.0f/9.0f, 3.0f/9.0f, 4.0f/9.0f,
    5.0f/9.0f, 6.0f/9.0f, 7.0f/9.0f, 8.0f/9.0f
};

__device__ __forceinline__ void basis_eval(float t, float* bb){
    bb[0] = 1.0f; bb[1] = t; bb[2] = t*t; bb[3] = bb[2]*t;
#pragma unroll
    for (int j = 0; j < 8; j++){
        float d = fmaxf(t - c_knots[j], 0.0f);
        bb[4+j] = d*d*d;
    }
}

__device__ __forceinline__ void mma_f16(float* c, const uint32_t* a, uint32_t b0, uint32_t b1){
    asm volatile(
        "mma.sync.aligned.m16n8k16.row.col.f32.f16.f16.f32 "
        "{%0,%1,%2,%3},{%4,%5,%6,%7},{%8,%9},{%0,%1,%2,%3};"
        : "+f"(c[0]), "+f"(c[1]), "+f"(c[2]), "+f"(c[3])
        : "r"(a[0]), "r"(a[1]), "r"(a[2]), "r"(a[3]), "r"(b0), "r"(b1));
}
__device__ __forceinline__ uint32_t smem_u32(const void* p){
    uint32_t a;
    asm("{ .reg .u64 t; cvta.to.shared.u64 t, %1; cvt.u32.u64 %0, t; }" : "=r"(a) : "l"(p));
    return a;
}
__device__ __forceinline__ void ldsm4(uint32_t* r, uint32_t a){
    asm volatile("ldmatrix.sync.aligned.m8n8.x4.shared.b16 {%0,%1,%2,%3}, [%4];"
        : "=r"(r[0]), "=r"(r[1]), "=r"(r[2]), "=r"(r[3]) : "r"(a));
}

// ---------------- parallel bin setup ----------------
__global__ void bins_zero(){
    if (threadIdx.x < NBINS) g_bincnt[threadIdx.x] = 0;
}
__global__ void bins_hist(const float* __restrict__ T){
    const int tid = blockIdx.x * blockDim.x + threadIdx.x;
    const int lane = threadIdx.x & 31;
    for (int i = tid; i < NROWS; i += gridDim.x * blockDim.x){
        int b = (int)(T[i] * 9.0f); b = b < 0 ? 0 : (b > 8 ? 8 : b);
        unsigned m = __match_any_sync(__activemask(), b);
        if (lane == __ffs(m) - 1) atomicAdd(&g_bincnt[b], __popc(m));
    }
}
__global__ void bins_scan(){
    if (threadIdx.x == 0){
        int off = 0, nt = 0;
        for (int b = 0; b < NBINS; b++){
            g_binstart[b] = off;
            g_cur[b] = off;
            int cnt = g_bincnt[b];
            for (int ms = 0; ms < cnt; ms += 128){
                g_tilebin[nt] = b; g_tilem0[nt] = off + ms; nt++;
            }
            off += cnt;
        }
        g_binstart[NBINS] = off;
        g_ntiles = nt;
    }
}
__global__ void bins_scatter(const float* __restrict__ T){
    const int tid = blockIdx.x * blockDim.x + threadIdx.x;
    const int lane = threadIdx.x & 31;
    for (int i = tid; i < NROWS; i += gridDim.x * blockDim.x){
        float t = T[i];
        int b = (int)(t * 9.0f); b = b < 0 ? 0 : (b > 8 ? 8 : b);
        unsigned msk = __activemask();
        unsigned m = __match_any_sync(msk, b);
        int ldr = __ffs(m) - 1;
        int pre = __popc(m & ((1u << lane) - 1u));
        int base = 0;
        if (lane == ldr) base = atomicAdd(&g_cur[b], __popc(m));
        base = __shfl_sync(msk, base, ldr);
        g_perm[base + pre] = i;
        g_tp[base + pre] = t;
    }
}

// ---------------- prep: W(3072x256) -> per-bin poly weights [bin][o][j*256+i], fp16 ----------------
__global__ void prep_w(const float* __restrict__ W, __half* __restrict__ Hi){
    const int i = threadIdx.x, o = blockIdx.x;
    float w[12];
#pragma unroll
    for (int s = 0; s < 12; s++) w[s] = W[(size_t)(s*256 + i)*256 + o];
    float p[4] = {w[0], w[1], w[2], w[3]};
    for (int bin = 0; bin < NBINS; bin++){
        if (bin >= 1){
            float k = (float)bin / 9.0f, ww = w[3 + bin];
            p[3] += ww; p[2] -= 3.0f*k*ww; p[1] += 3.0f*k*k*ww; p[0] -= k*k*k*ww;
        }
#pragma unroll
        for (int j = 0; j < 4; j++)
            Hi[((size_t)bin*256 + o)*1024 + j*256 + i] = __float2half_rn(p[j]);
    }
}

__global__ void prep_b(const float* __restrict__ Bv, float* __restrict__ Pb){
    const int o = threadIdx.x;
    float w[12];
#pragma unroll
    for (int s = 0; s < 12; s++) w[s] = Bv[s*256 + o];
    float p[4] = {w[0], w[1], w[2], w[3]};
    for (int bin = 0; bin < NBINS; bin++){
        if (bin >= 1){
            float k = (float)bin / 9.0f, ww = w[3 + bin];
            p[3] += ww; p[2] -= 3.0f*k*ww; p[1] += 3.0f*k*k*ww; p[0] -= k*k*k*ww;
        }
#pragma unroll
        for (int j = 0; j < 4; j++) Pb[(bin*4 + j)*256 + o] = p[j];
    }
}

// ---------------- GEMM: Y[pos,n] = sum_k (t^j x_i) P[bin,k,n] + bias, fp16 single-pass ----------------
template<bool GATHER, bool RELU>
__global__ void __launch_bounds__(256) vc_gemm(
    const float* __restrict__ Xsrc, const __half* __restrict__ WHi,
    const float* __restrict__ Pb, float* __restrict__ Y)
{
    const int tile = blockIdx.x;
    if (tile >= g_ntiles) return;
    __shared__ __half Ah[128*ASTR];
    __shared__ __half Bh[128*ASTR];
    __shared__ float spw[128][4];
    __shared__ float pbs[4][128];

    const int tid = threadIdx.x, wid = tid >> 5, lane = tid & 31;
    const int bin = g_tilebin[tile];
    const int m0  = g_tilem0[tile];
    const int rows = min(128, g_binstart[bin + 1] - m0);
    const int n0 = blockIdx.y * 128;

    if (tid < 128){
        float t = (tid < rows) ? g_tp[m0 + tid] : 0.0f;
        float e = (tid < rows) ? 1.0f : 0.0f;
        spw[tid][0] = e; spw[tid][1] = e*t; spw[tid][2] = e*t*t; spw[tid][3] = e*t*t*t;
    }
#pragma unroll
    for (int q = 0; q < 2; q++){
        int idx = q*256 + tid;
        pbs[idx >> 7][idx & 127] = Pb[(bin*4 + (idx >> 7))*256 + n0 + (idx & 127)];
    }

    const int r = tid >> 1, h = tid & 1;
    const int rs = min(r, rows - 1);
    const float* xrow = Xsrc + (size_t)(GATHER ? g_perm[m0 + rs] : (m0 + rs)) * 256 + h*16;
    const size_t wbase = (size_t)bin * 256 * 1024;

    __syncthreads();

    float4 xr[4];
    uint4 bh[2];
    {   // prefetch slab 0
#pragma unroll
        for (int q = 0; q < 4; q++) xr[q] = *(const float4*)(xrow + q*4);
#pragma unroll
        for (int it = 0; it < 2; it++){
            int idx = it*256 + tid, o = idx >> 2, q = idx & 3;
            bh[it] = *(const uint4*)(WHi + wbase + (size_t)(n0 + o)*1024 + q*8);
        }
    }

    const int wm = (wid >> 1) * 32, wn = (wid & 1) * 64;
    const int lr = lane >> 2, lk = lane & 3;
    // ldmatrix lane addresses (byte offsets into smem rows)
    const uint32_t sAh = smem_u32(Ah), sBh = smem_u32(Bh);
    const uint32_t aAddrBase = sAh + (uint32_t)(wm + (lane & 15))*(ASTR*2) + (uint32_t)(lane >> 4)*16;
    const uint32_t bAddrBase = sBh + (uint32_t)(wn + (lane >> 4)*8 + (lane & 7))*(ASTR*2)
                                   + (uint32_t)((lane >> 3) & 1)*16;

    float acc[2][8][4];
#pragma unroll
    for (int a = 0; a < 2; a++)
#pragma unroll
        for (int b = 0; b < 8; b++)
#pragma unroll
            for (int c = 0; c < 4; c++) acc[a][b][c] = 0.0f;

    for (int s = 0; s < 32; s++){
        const int j = s >> 3;
        __syncthreads();
        // commit A (t^j * x -> fp16) and B to smem
        {
            const float pw = spw[r][j];
            const float* xe = (const float*)xr;
#pragma unroll
            for (int p = 0; p < 2; p++){
                uint32_t hf[4];
#pragma unroll
                for (int e = 0; e < 4; e++){
                    __half2 h2 = __floats2half2_rn(pw * xe[p*8 + e*2], pw * xe[p*8 + e*2 + 1]);
                    hf[e] = *(uint32_t*)&h2;
                }
                *(uint4*)((char*)Ah + r*(ASTR*2) + h*32 + p*16) = make_uint4(hf[0], hf[1], hf[2], hf[3]);
            }
#pragma unroll
            for (int it = 0; it < 2; it++){
                int idx = it*256 + tid, o = idx >> 2, q = idx & 3;
                *(uint4*)((char*)Bh + o*(ASTR*2) + q*16) = bh[it];
            }
        }
        // prefetch slab s+1
        if (s < 31){
            const int sn = s + 1, i0 = (sn & 7) * 32, jn = sn >> 3;
#pragma unroll
            for (int q = 0; q < 4; q++) xr[q] = *(const float4*)(xrow + i0 + q*4);
#pragma unroll
            for (int it = 0; it < 2; it++){
                int idx = it*256 + tid, o = idx >> 2, q = idx & 3;
                bh[it] = *(const uint4*)(WHi + wbase + (size_t)(n0 + o)*1024 + jn*256 + i0 + q*8);
            }
        }
        __syncthreads();
        // MMA on slab s via ldmatrix fragments
#pragma unroll
        for (int kk = 0; kk < 2; kk++){
            uint32_t af[2][4];
            ldsm4(af[0], aAddrBase + kk*32);
            ldsm4(af[1], aAddrBase + 16*(ASTR*2) + kk*32);
#pragma unroll
            for (int np = 0; np < 4; np++){
                uint32_t bf[4];
                ldsm4(bf, bAddrBase + np*16*(ASTR*2) + kk*32);
#pragma unroll
                for (int mt = 0; mt < 2; mt++){
                    mma_f16(acc[mt][np*2 + 0], af[mt], bf[0], bf[1]);
                    mma_f16(acc[mt][np*2 + 1], af[mt], bf[2], bf[3]);
                }
            }
        }
    }

    // epilogue: + poly bias, relu, store (permuted row space)
#pragma unroll
    for (int mt = 0; mt < 2; mt++){
#pragma unroll
        for (int half = 0; half < 2; half++){
            int rr = wm + mt*16 + lr + half*8;
            if (rr >= rows) continue;
            float pw0 = spw[rr][0], pw1 = spw[rr][1], pw2 = spw[rr][2], pw3 = spw[rr][3];
            float* yp = Y + (size_t)(m0 + rr) * 256 + n0;
#pragma unroll
            for (int nt = 0; nt < 8; nt++){
                int col = wn + nt*8 + lk*2;
                float b0 = pw0*pbs[0][col]   + pw1*pbs[1][col]   + pw2*pbs[2][col]   + pw3*pbs[3][col];
                float b1 = pw0*pbs[0][col+1] + pw1*pbs[1][col+1] + pw2*pbs[2][col+1] + pw3*pbs[3][col+1];
                float v0 = acc[mt][nt][half*2 + 0] + b0;
                float v1 = acc[mt][nt][half*2 + 1] + b1;
                if (RELU){ v0 = fmaxf(v0, 0.0f); v1 = fmaxf(v1, 0.0f); }
                *(float2*)(yp + col) = make_float2(v0, v1);
            }
        }
    }
}

// ---------------- head ----------------
__global__ void head_kernel(const float* __restrict__ X,
                            const float* __restrict__ W2, const float* __restrict__ b2,
                            float* __restrict__ out)
{
    const int warp = threadIdx.x >> 5, lane = threadIdx.x & 31;
    const int pos = blockIdx.x * 8 + warp;
    float bb[12];
    basis_eval(g_tp[pos], bb);
    float acc = 0.0f;
#pragma unroll
    for (int ii = 0; ii < 8; ii++){
        const int i = lane + 32*ii;
        float w = 0.0f;
#pragma unroll
        for (int s = 0; s < 12; s++) w = fmaf(bb[s], W2[s*256 + i], w);
        acc = fmaf(X[(size_t)pos*256 + i], w, acc);
    }
#pragma unroll
    for (int off = 16; off; off >>= 1) acc += __shfl_xor_sync(0xffffffffu, acc, off);
    if (lane == 0){
        float bias = 0.0f;
#pragma unroll
        for (int s = 0; s < 12; s++) bias = fmaf(bb[s], b2[s], bias);
        out[g_perm[pos]] = acc + bias;
    }
}

extern "C" void kernel_launch(void* const* d_in, const int* in_sizes, int n_in,
                              void* d_out, int out_size)
{
    const float* T  = (const float*)d_in[0];
    const float* X  = (const float*)d_in[1];
    const float* W0 = (const float*)d_in[2];
    const float* b0 = (const float*)d_in[3];
    const float* W1 = (const float*)d_in[4];
    const float* b1 = (const float*)d_in[5];
    const float* W2 = (const float*)d_in[6];
    const float* b2 = (const float*)d_in[7];
    float* out = (float*)d_out;

    float *buf0, *buf1, *pb0, *pb1;
    __half *wp0, *wp1;
    cudaGetSymbolAddress((void**)&buf0, g_buf0);
    cudaGetSymbolAddress((void**)&buf1, g_buf1);
    cudaGetSymbolAddress((void**)&wp0, g_Wp0);
    cudaGetSymbolAddress((void**)&wp1, g_Wp1);
    cudaGetSymbolAddress((void**)&pb0, g_Pb0);
    cudaGetSymbolAddress((void**)&pb1, g_Pb1);

    bins_zero<<<1, 32>>>();
    bins_hist<<<64, 512>>>(T);
    bins_scan<<<1, 32>>>();
    bins_scatter<<<64, 512>>>(T);

    prep_w<<<256, 256>>>(W0, wp0);
    prep_w<<<256, 256>>>(W1, wp1);
    prep_b<<<1, 256>>>(b0, pb0);
    prep_b<<<1, 256>>>(b1, pb1);

    dim3 grid(MAXTILES, 2);
    vc_gemm<true,  true><<<grid, 256>>>(X,    wp0, pb0, buf0);
    vc_gemm<false, true><<<grid, 256>>>(buf0, wp1, pb1, buf1);
    head_kernel<<<NROWS / 8, 256>>>(buf1, W2, b2, out);
}

// round 8
// speedup vs baseline: 16.5109x; 1.1574x over previous
#include <cuda_runtime.h>
#include <cuda_bf16.h>
#include <cuda_fp16.h>
#include <math.h>
#include <stdint.h>

#define NROWS 32768
#define NBINS 9
#define MAXTILES 272
#define ASTRA 264            /* A smem: halves per row (528 B) */
#define BSTR  40             /* B smem: halves per row (80 B) */

/* dynamic smem layout (bytes) */
#define OFF_A    0
#define OFF_B    67584       /* 128*264*2 */
#define BBUF_SZ  10240       /* 128*40*2  */
#define OFF_SPW  88064       /* OFF_B + 2*BBUF_SZ */
#define OFF_PBS  90112
#define SMEM_SZ  92160

__device__ float g_buf0[(size_t)NROWS * 256];
__device__ float g_buf1[(size_t)NROWS * 256];
__device__ __half g_Wp0[(size_t)NBINS * 256 * 1024];
__device__ __half g_Wp1[(size_t)NBINS * 256 * 1024];
__device__ float g_Pb0[NBINS * 4 * 256];
__device__ float g_Pb1[NBINS * 4 * 256];
__device__ int   g_perm[NROWS];
__device__ float g_tp[NROWS];
__device__ int   g_binstart[NBINS + 1];
__device__ int   g_bincnt[NBINS];
__device__ int   g_cur[NBINS];
__device__ int   g_tilebin[MAXTILES];
__device__ int   g_tilem0[MAXTILES];
__device__ int   g_ntiles;

__constant__ float c_knots[8] = {
    1.0f/9.0f, 2.0f/9.0f, 3.0f/9.0f, 4.0f/9.0f,
    5.0f/9.0f, 6.0f/9.0f, 7.0f/9.0f, 8.0f/9.0f
};

__device__ __forceinline__ void basis_eval(float t, float* bb){
    bb[0] = 1.0f; bb[1] = t; bb[2] = t*t; bb[3] = bb[2]*t;
#pragma unroll
    for (int j = 0; j < 8; j++){
        float d = fmaxf(t - c_knots[j], 0.0f);
        bb[4+j] = d*d*d;
    }
}
__device__ __forceinline__ void mma_f16(float* c, const uint32_t* a, uint32_t b0, uint32_t b1){
    asm volatile(
        "mma.sync.aligned.m16n8k16.row.col.f32.f16.f16.f32 "
        "{%0,%1,%2,%3},{%4,%5,%6,%7},{%8,%9},{%0,%1,%2,%3};"
        : "+f"(c[0]), "+f"(c[1]), "+f"(c[2]), "+f"(c[3])
        : "r"(a[0]), "r"(a[1]), "r"(a[2]), "r"(a[3]), "r"(b0), "r"(b1));
}
__device__ __forceinline__ uint32_t smem_u32(const void* p){
    uint32_t a;
    asm("{ .reg .u64 t; cvta.to.shared.u64 t, %1; cvt.u32.u64 %0, t; }" : "=r"(a) : "l"(p));
    return a;
}
__device__ __forceinline__ void ldsm4(uint32_t* r, uint32_t a){
    asm volatile("ldmatrix.sync.aligned.m8n8.x4.shared.b16 {%0,%1,%2,%3}, [%4];"
        : "=r"(r[0]), "=r"(r[1]), "=r"(r[2]), "=r"(r[3]) : "r"(a));
}

// ---------------- bin setup ----------------
__global__ void bins_hist(const float* __restrict__ T){
    const int tid = blockIdx.x * blockDim.x + threadIdx.x;
    const int lane = threadIdx.x & 31;
    for (int i = tid; i < NROWS; i += gridDim.x * blockDim.x){
        int b = (int)(T[i] * 9.0f); b = b < 0 ? 0 : (b > 8 ? 8 : b);
        unsigned m = __match_any_sync(__activemask(), b);
        if (lane == __ffs(m) - 1) atomicAdd(&g_bincnt[b], __popc(m));
    }
}
__global__ void bins_scan(){
    if (threadIdx.x == 0){
        int off = 0, nt = 0;
        for (int b = 0; b < NBINS; b++){
            g_binstart[b] = off;
            g_cur[b] = off;
            int cnt = g_bincnt[b];
            for (int ms = 0; ms < cnt; ms += 128){
                g_tilebin[nt] = b; g_tilem0[nt] = off + ms; nt++;
            }
            off += cnt;
        }
        g_binstart[NBINS] = off;
        g_ntiles = nt;
    }
}
__global__ void bins_scatter(const float* __restrict__ T){
    const int tid = blockIdx.x * blockDim.x + threadIdx.x;
    const int lane = threadIdx.x & 31;
    for (int i = tid; i < NROWS; i += gridDim.x * blockDim.x){
        float t = T[i];
        int b = (int)(t * 9.0f); b = b < 0 ? 0 : (b > 8 ? 8 : b);
        unsigned msk = __activemask();
        unsigned m = __match_any_sync(msk, b);
        int ldr = __ffs(m) - 1;
        int pre = __popc(m & ((1u << lane) - 1u));
        int base = 0;
        if (lane == ldr) base = atomicAdd(&g_cur[b], __popc(m));
        base = __shfl_sync(msk, base, ldr);
        g_perm[base + pre] = i;
        g_tp[base + pre] = t;
    }
}

// ---------------- prep: weights + biases, both layers, one launch ----------------
__global__ void prep_all(const float* __restrict__ W0, const float* __restrict__ b0,
                         const float* __restrict__ W1, const float* __restrict__ b1){
    const int layer = blockIdx.y;
    const float* W  = layer ? W1 : W0;
    const float* Bv = layer ? b1 : b0;
    __half* Hi = layer ? g_Wp1 : g_Wp0;
    float*  Pb = layer ? g_Pb1 : g_Pb0;
    const int i = threadIdx.x;
    if (blockIdx.x < 256){
        const int o = blockIdx.x;
        float w[12];
#pragma unroll
        for (int s = 0; s < 12; s++) w[s] = W[(size_t)(s*256 + i)*256 + o];
        float p[4] = {w[0], w[1], w[2], w[3]};
        for (int bin = 0; bin < NBINS; bin++){
            if (bin >= 1){
                float k = (float)bin / 9.0f, ww = w[3 + bin];
                p[3] += ww; p[2] -= 3.0f*k*ww; p[1] += 3.0f*k*k*ww; p[0] -= k*k*k*ww;
            }
#pragma unroll
            for (int j = 0; j < 4; j++)
                Hi[((size_t)bin*256 + o)*1024 + j*256 + i] = __float2half_rn(p[j]);
        }
    } else {
        const int o = i;
        float w[12];
#pragma unroll
        for (int s = 0; s < 12; s++) w[s] = Bv[s*256 + o];
        float p[4] = {w[0], w[1], w[2], w[3]};
        for (int bin = 0; bin < NBINS; bin++){
            if (bin >= 1){
                float k = (float)bin / 9.0f, ww = w[3 + bin];
                p[3] += ww; p[2] -= 3.0f*k*ww; p[1] += 3.0f*k*k*ww; p[0] -= k*k*k*ww;
            }
#pragma unroll
            for (int j = 0; j < 4; j++) Pb[(bin*4 + j)*256 + o] = p[j];
        }
    }
}

// ---------------- GEMM with Horner-over-accumulator ----------------
// Y[pos,n] = ((x@P3)·t + x@P2)·t + ... + bias; A=fp16(x) built once.
template<bool GATHER, bool RELU>
__global__ void __launch_bounds__(256) vc_gemm(
    const float* __restrict__ Xsrc, const __half* __restrict__ WHi,
    const float* __restrict__ Pb, float* __restrict__ Y)
{
    const int tile = blockIdx.x;
    if (tile >= g_ntiles) return;
    extern __shared__ __align__(16) char smem[];
    __half* Ah = (__half*)(smem + OFF_A);
    float* spw = (float*)(smem + OFF_SPW);
    float* pbs = (float*)(smem + OFF_PBS);

    const int tid = threadIdx.x, wid = tid >> 5, lane = tid & 31;
    const int bin = g_tilebin[tile];
    const int m0  = g_tilem0[tile];
    const int rows = min(128, g_binstart[bin + 1] - m0);
    const int n0 = blockIdx.y * 128;

    if (tid < 128){
        float t = (tid < rows) ? g_tp[m0 + tid] : 0.0f;
        float e = (tid < rows) ? 1.0f : 0.0f;
        spw[tid*4+0] = e; spw[tid*4+1] = e*t; spw[tid*4+2] = e*t*t; spw[tid*4+3] = e*t*t*t;
    }
#pragma unroll
    for (int q = 0; q < 2; q++){
        int idx = q*256 + tid;
        pbs[idx] = Pb[(bin*4 + (idx >> 7))*256 + n0 + (idx & 127)];
    }

    // ---- build A (fp16(x), full 128x256) once: each thread covers its 128-col half ----
    const int r = tid >> 1, h = tid & 1;
    const int rs = min(r, rows - 1);
    const float* xrow = Xsrc + (size_t)(GATHER ? g_perm[m0 + rs] : (m0 + rs)) * 256 + h*128;
#pragma unroll
    for (int q8 = 0; q8 < 16; q8++){
        float4 a = *(const float4*)(xrow + q8*8);
        float4 b = *(const float4*)(xrow + q8*8 + 4);
        __half2 h0 = __floats2half2_rn(a.x, a.y), h1 = __floats2half2_rn(a.z, a.w);
        __half2 h2 = __floats2half2_rn(b.x, b.y), h3 = __floats2half2_rn(b.z, b.w);
        *(uint4*)((char*)Ah + r*(ASTRA*2) + h*256 + q8*16) =
            make_uint4(*(uint32_t*)&h0, *(uint32_t*)&h1, *(uint32_t*)&h2, *(uint32_t*)&h3);
    }

    // ---- B prefetch slab 0 (j=3, ic=0) ----
    const size_t wbase = (size_t)bin * 256 * 1024;
    uint4 bh[2];
#pragma unroll
    for (int it = 0; it < 2; it++){
        int idx = it*256 + tid, o = idx >> 2, q = idx & 3;
        bh[it] = *(const uint4*)(WHi + wbase + (size_t)(n0 + o)*1024 + 3*256 + q*8);
    }
#pragma unroll
    for (int it = 0; it < 2; it++){
        int idx = it*256 + tid, o = idx >> 2, q = idx & 3;
        *(uint4*)(smem + OFF_B + o*(BSTR*2) + q*16) = bh[it];
    }
    __syncthreads();

    const int wm = (wid >> 1) * 32, wn = (wid & 1) * 64;
    const int lr = lane >> 2, lk = lane & 3;
    const uint32_t sA = smem_u32(Ah);
    const uint32_t aAddrBase = sA + (uint32_t)(wm + (lane & 15))*(ASTRA*2) + (uint32_t)(lane >> 4)*16;
    const uint32_t bAddrBase = smem_u32(smem + OFF_B)
                             + (uint32_t)(wn + (lane >> 4)*8 + (lane & 7))*(BSTR*2)
                             + (uint32_t)((lane >> 3) & 1)*16;
    float tA[2][2];
#pragma unroll
    for (int mt = 0; mt < 2; mt++){
        tA[mt][0] = spw[(wm + mt*16 + lr)*4 + 1];
        tA[mt][1] = spw[(wm + mt*16 + lr + 8)*4 + 1];
    }

    float acc[2][8][4];
#pragma unroll
    for (int a = 0; a < 2; a++)
#pragma unroll
        for (int b = 0; b < 8; b++)
#pragma unroll
            for (int c = 0; c < 4; c++) acc[a][b][c] = 0.0f;

    for (int s = 0; s < 32; s++){
        const int buf = s & 1;
        const int ic = s & 7;
        // prefetch slab s+1
        if (s < 31){
            const int sn = s + 1;
            const int koff = (3 - (sn >> 3))*256 + (sn & 7)*32;
#pragma unroll
            for (int it = 0; it < 2; it++){
                int idx = it*256 + tid, o = idx >> 2, q = idx & 3;
                bh[it] = *(const uint4*)(WHi + wbase + (size_t)(n0 + o)*1024 + koff + q*8);
            }
        }
        // MMA on slab s (B from buf, A cols ic*32..+32)
#pragma unroll
        for (int kk = 0; kk < 2; kk++){
            uint32_t af[2][4];
            ldsm4(af[0], aAddrBase + ic*64 + kk*32);
            ldsm4(af[1], aAddrBase + 16*(ASTRA*2) + ic*64 + kk*32);
#pragma unroll
            for (int np = 0; np < 4; np++){
                uint32_t bf[4];
                ldsm4(bf, bAddrBase + buf*BBUF_SZ + np*16*(BSTR*2) + kk*32);
#pragma unroll
                for (int mt = 0; mt < 2; mt++){
                    mma_f16(acc[mt][np*2 + 0], af[mt], bf[0], bf[1]);
                    mma_f16(acc[mt][np*2 + 1], af[mt], bf[2], bf[3]);
                }
            }
        }
        // commit prefetched B into other buffer
        if (s < 31){
#pragma unroll
            for (int it = 0; it < 2; it++){
                int idx = it*256 + tid, o = idx >> 2, q = idx & 3;
                *(uint4*)(smem + OFF_B + (buf ^ 1)*BBUF_SZ + o*(BSTR*2) + q*16) = bh[it];
            }
        }
        // Horner transition at end of each j-block (except last)
        if ((s & 7) == 7 && s < 31){
#pragma unroll
            for (int mt = 0; mt < 2; mt++)
#pragma unroll
                for (int nt = 0; nt < 8; nt++){
                    acc[mt][nt][0] *= tA[mt][0];
                    acc[mt][nt][1] *= tA[mt][0];
                    acc[mt][nt][2] *= tA[mt][1];
                    acc[mt][nt][3] *= tA[mt][1];
                }
        }
        __syncthreads();
    }

    // epilogue: + poly bias, relu, store
#pragma unroll
    for (int mt = 0; mt < 2; mt++){
#pragma unroll
        for (int half = 0; half < 2; half++){
            int rr = wm + mt*16 + lr + half*8;
            if (rr >= rows) continue;
            float pw0 = spw[rr*4+0], pw1 = spw[rr*4+1], pw2 = spw[rr*4+2], pw3 = spw[rr*4+3];
            float* yp = Y + (size_t)(m0 + rr) * 256 + n0;
#pragma unroll
            for (int nt = 0; nt < 8; nt++){
                int col = wn + nt*8 + lk*2;
                float b0 = pw0*pbs[col]     + pw1*pbs[128+col]   + pw2*pbs[256+col]   + pw3*pbs[384+col];
                float b1 = pw0*pbs[col+1]   + pw1*pbs[128+col+1] + pw2*pbs[256+col+1] + pw3*pbs[384+col+1];
                float v0 = acc[mt][nt][half*2 + 0] + b0;
                float v1 = acc[mt][nt][half*2 + 1] + b1;
                if (RELU){ v0 = fmaxf(v0, 0.0f); v1 = fmaxf(v1, 0.0f); }
                *(float2*)(yp + col) = make_float2(v0, v1);
            }
        }
    }
}

// ---------------- head ----------------
__global__ void head_kernel(const float* __restrict__ X,
                            const float* __restrict__ W2, const float* __restrict__ b2,
                            float* __restrict__ out)
{
    const int warp = threadIdx.x >> 5, lane = threadIdx.x & 31;
    const int pos = blockIdx.x * 8 + warp;
    float bb[12];
    basis_eval(g_tp[pos], bb);
    float acc = 0.0f;
#pragma unroll
    for (int ii = 0; ii < 8; ii++){
        const int i = lane + 32*ii;
        float w = 0.0f;
#pragma unroll
        for (int s = 0; s < 12; s++) w = fmaf(bb[s], W2[s*256 + i], w);
        acc = fmaf(X[(size_t)pos*256 + i], w, acc);
    }
#pragma unroll
    for (int off = 16; off; off >>= 1) acc += __shfl_xor_sync(0xffffffffu, acc, off);
    if (lane == 0){
        float bias = 0.0f;
#pragma unroll
        for (int s = 0; s < 12; s++) bias = fmaf(bb[s], b2[s], bias);
        out[g_perm[pos]] = acc + bias;
    }
}

extern "C" void kernel_launch(void* const* d_in, const int* in_sizes, int n_in,
                              void* d_out, int out_size)
{
    const float* T  = (const float*)d_in[0];
    const float* X  = (const float*)d_in[1];
    const float* W0 = (const float*)d_in[2];
    const float* b0 = (const float*)d_in[3];
    const float* W1 = (const float*)d_in[4];
    const float* b1 = (const float*)d_in[5];
    const float* W2 = (const float*)d_in[6];
    const float* b2 = (const float*)d_in[7];
    float* out = (float*)d_out;

    float *buf0, *buf1, *pb0, *pb1;
    __half *wp0, *wp1;
    int* bincnt;
    cudaGetSymbolAddress((void**)&buf0, g_buf0);
    cudaGetSymbolAddress((void**)&buf1, g_buf1);
    cudaGetSymbolAddress((void**)&wp0, g_Wp0);
    cudaGetSymbolAddress((void**)&wp1, g_Wp1);
    cudaGetSymbolAddress((void**)&pb0, g_Pb0);
    cudaGetSymbolAddress((void**)&pb1, g_Pb1);
    cudaGetSymbolAddress((void**)&bincnt, g_bincnt);

    cudaFuncSetAttribute(vc_gemm<true,  true>, cudaFuncAttributeMaxDynamicSharedMemorySize, SMEM_SZ);
    cudaFuncSetAttribute(vc_gemm<false, true>, cudaFuncAttributeMaxDynamicSharedMemorySize, SMEM_SZ);

    cudaMemsetAsync(bincnt, 0, NBINS * sizeof(int), 0);
    bins_hist<<<64, 512>>>(T);
    bins_scan<<<1, 32>>>();
    bins_scatter<<<64, 512>>>(T);
    prep_all<<<dim3(257, 2), 256>>>(W0, b0, W1, b1);

    dim3 grid(MAXTILES, 2);
    vc_gemm<true,  true><<<grid, 256, SMEM_SZ>>>(X,    wp0, pb0, buf0);
    vc_gemm<false, true><<<grid, 256, SMEM_SZ>>>(buf0, wp1, pb1, buf1);
    head_kernel<<<NROWS / 8, 256>>>(buf1, W2, b2, out);
}

// round 9
// speedup vs baseline: 16.7790x; 1.0162x over previous
#include <cuda_runtime.h>
#include <cuda_bf16.h>
#include <cuda_fp16.h>
#include <math.h>
#include <stdint.h>

#define NROWS 32768
#define NBINS 9
#define MAXTILES 272
#define ASTRA 264            /* A smem: halves per row (528 B) */
#define BSTR  40             /* B smem: halves per row (80 B) */

/* dynamic smem layout (bytes) */
#define OFF_A    0
#define OFF_B    67584       /* 128*264*2 */
#define BBUF_SZ  10240       /* 128*40*2  */
#define OFF_SPW  88064       /* OFF_B + 2*BBUF_SZ */
#define OFF_PBS  90112
#define SMEM_SZ  92160

__device__ float g_buf0[(size_t)NROWS * 256];
__device__ float g_buf1[(size_t)NROWS * 256];
__device__ float g_Wt0[(size_t)256 * 3072];
__device__ float g_Wt1[(size_t)256 * 3072];
__device__ __half g_Wp0[(size_t)NBINS * 256 * 1024];
__device__ __half g_Wp1[(size_t)NBINS * 256 * 1024];
__device__ float g_Pb0[NBINS * 4 * 256];
__device__ float g_Pb1[NBINS * 4 * 256];
__device__ int   g_perm[NROWS];
__device__ float g_tp[NROWS];
__device__ int   g_binstart[NBINS + 1];
__device__ int   g_bincnt[NBINS];
__device__ int   g_cur[NBINS];
__device__ int   g_tilebin[MAXTILES];
__device__ int   g_tilem0[MAXTILES];
__device__ int   g_ntiles;

__constant__ float c_knots[8] = {
    1.0f/9.0f, 2.0f/9.0f, 3.0f/9.0f, 4.0f/9.0f,
    5.0f/9.0f, 6.0f/9.0f, 7.0f/9.0f, 8.0f/9.0f
};

__device__ __forceinline__ void basis_eval(float t, float* bb){
    bb[0] = 1.0f; bb[1] = t; bb[2] = t*t; bb[3] = bb[2]*t;
#pragma unroll
    for (int j = 0; j < 8; j++){
        float d = fmaxf(t - c_knots[j], 0.0f);
        bb[4+j] = d*d*d;
    }
}
__device__ __forceinline__ void mma_f16(float* c, const uint32_t* a, uint32_t b0, uint32_t b1){
    asm volatile(
        "mma.sync.aligned.m16n8k16.row.col.f32.f16.f16.f32 "
        "{%0,%1,%2,%3},{%4,%5,%6,%7},{%8,%9},{%0,%1,%2,%3};"
        : "+f"(c[0]), "+f"(c[1]), "+f"(c[2]), "+f"(c[3])
        : "r"(a[0]), "r"(a[1]), "r"(a[2]), "r"(a[3]), "r"(b0), "r"(b1));
}
__device__ __forceinline__ uint32_t smem_u32(const void* p){
    uint32_t a;
    asm("{ .reg .u64 t; cvta.to.shared.u64 t, %1; cvt.u32.u64 %0, t; }" : "=r"(a) : "l"(p));
    return a;
}
__device__ __forceinline__ void ldsm4(uint32_t* r, uint32_t a){
    asm volatile("ldmatrix.sync.aligned.m8n8.x4.shared.b16 {%0,%1,%2,%3}, [%4];"
        : "=r"(r[0]), "=r"(r[1]), "=r"(r[2]), "=r"(r[3]) : "r"(a));
}

// ---------------- bin setup ----------------
__global__ void bins_hist(const float* __restrict__ T){
    const int tid = blockIdx.x * blockDim.x + threadIdx.x;
    const int lane = threadIdx.x & 31;
    for (int i = tid; i < NROWS; i += gridDim.x * blockDim.x){
        int b = (int)(T[i] * 9.0f); b = b < 0 ? 0 : (b > 8 ? 8 : b);
        unsigned m = __match_any_sync(__activemask(), b);
        if (lane == __ffs(m) - 1) atomicAdd(&g_bincnt[b], __popc(m));
    }
}
__global__ void bins_scan(){
    if (threadIdx.x == 0){
        int off = 0, nt = 0;
        for (int b = 0; b < NBINS; b++){
            g_binstart[b] = off;
            g_cur[b] = off;
            int cnt = g_bincnt[b];
            for (int ms = 0; ms < cnt; ms += 128){
                g_tilebin[nt] = b; g_tilem0[nt] = off + ms; nt++;
            }
            off += cnt;
        }
        g_binstart[NBINS] = off;
        g_ntiles = nt;
    }
}
__global__ void bins_scatter(const float* __restrict__ T){
    const int tid = blockIdx.x * blockDim.x + threadIdx.x;
    const int lane = threadIdx.x & 31;
    for (int i = tid; i < NROWS; i += gridDim.x * blockDim.x){
        float t = T[i];
        int b = (int)(t * 9.0f); b = b < 0 ? 0 : (b > 8 ? 8 : b);
        unsigned msk = __activemask();
        unsigned m = __match_any_sync(msk, b);
        int ldr = __ffs(m) - 1;
        int pre = __popc(m & ((1u << lane) - 1u));
        int base = 0;
        if (lane == ldr) base = atomicAdd(&g_cur[b], __popc(m));
        base = __shfl_sync(msk, base, ldr);
        g_perm[base + pre] = i;
        g_tp[base + pre] = t;
    }
}

// ---------------- transpose W (3072x256) -> Wt (256x3072), both layers ----------------
__global__ void transpose_w(const float* __restrict__ W0, const float* __restrict__ W1){
    __shared__ float tile[32][33];
    const float* W = blockIdx.z ? W1 : W0;
    float* Wt = blockIdx.z ? g_Wt1 : g_Wt0;
    const int tx = threadIdx.x, ty = threadIdx.y;
    const int k0 = blockIdx.y * 32, o0 = blockIdx.x * 32;
#pragma unroll
    for (int q = 0; q < 4; q++)
        tile[ty + q*8][tx] = W[(size_t)(k0 + ty + q*8) * 256 + o0 + tx];
    __syncthreads();
#pragma unroll
    for (int q = 0; q < 4; q++)
        Wt[(size_t)(o0 + ty + q*8) * 3072 + k0 + tx] = tile[tx][ty + q*8];
}

// ---------------- prep: poly weights + biases (coalesced reads via Wt) ----------------
__global__ void prep_all(const float* __restrict__ b0, const float* __restrict__ b1){
    const int layer = blockIdx.y;
    const float* Wt = layer ? g_Wt1 : g_Wt0;
    const float* Bv = layer ? b1 : b0;
    __half* Hi = layer ? g_Wp1 : g_Wp0;
    float*  Pb = layer ? g_Pb1 : g_Pb0;
    const int i = threadIdx.x;
    if (blockIdx.x < 256){
        const int o = blockIdx.x;
        float w[12];
#pragma unroll
        for (int s = 0; s < 12; s++) w[s] = Wt[(size_t)o * 3072 + s*256 + i];
        float p[4] = {w[0], w[1], w[2], w[3]};
        for (int bin = 0; bin < NBINS; bin++){
            if (bin >= 1){
                float k = (float)bin / 9.0f, ww = w[3 + bin];
                p[3] += ww; p[2] -= 3.0f*k*ww; p[1] += 3.0f*k*k*ww; p[0] -= k*k*k*ww;
            }
#pragma unroll
            for (int j = 0; j < 4; j++)
                Hi[((size_t)bin*256 + o)*1024 + j*256 + i] = __float2half_rn(p[j]);
        }
    } else {
        const int o = i;
        float w[12];
#pragma unroll
        for (int s = 0; s < 12; s++) w[s] = Bv[s*256 + o];
        float p[4] = {w[0], w[1], w[2], w[3]};
        for (int bin = 0; bin < NBINS; bin++){
            if (bin >= 1){
                float k = (float)bin / 9.0f, ww = w[3 + bin];
                p[3] += ww; p[2] -= 3.0f*k*ww; p[1] += 3.0f*k*k*ww; p[0] -= k*k*k*ww;
            }
#pragma unroll
            for (int j = 0; j < 4; j++) Pb[(bin*4 + j)*256 + o] = p[j];
        }
    }
}

// ---------------- GEMM with Horner-over-accumulator, 2 CTAs/SM ----------------
template<bool GATHER, bool RELU>
__global__ void __launch_bounds__(256, 2) vc_gemm(
    const float* __restrict__ Xsrc, const __half* __restrict__ WHi,
    const float* __restrict__ Pb, float* __restrict__ Y)
{
    const int tile = blockIdx.x;
    if (tile >= g_ntiles) return;
    extern __shared__ __align__(16) char smem[];
    __half* Ah = (__half*)(smem + OFF_A);
    float* spw = (float*)(smem + OFF_SPW);
    float* pbs = (float*)(smem + OFF_PBS);

    const int tid = threadIdx.x, wid = tid >> 5, lane = tid & 31;
    const int bin = g_tilebin[tile];
    const int m0  = g_tilem0[tile];
    const int rows = min(128, g_binstart[bin + 1] - m0);
    const int n0 = blockIdx.y * 128;

    if (tid < 128){
        float t = (tid < rows) ? g_tp[m0 + tid] : 0.0f;
        float e = (tid < rows) ? 1.0f : 0.0f;
        spw[tid*4+0] = e; spw[tid*4+1] = e*t; spw[tid*4+2] = e*t*t; spw[tid*4+3] = e*t*t*t;
    }
#pragma unroll
    for (int q = 0; q < 2; q++){
        int idx = q*256 + tid;
        pbs[idx] = Pb[(bin*4 + (idx >> 7))*256 + n0 + (idx & 127)];
    }

    // ---- build A (fp16(x), full 128x256) once ----
    const int r = tid >> 1, h = tid & 1;
    const int rs = min(r, rows - 1);
    const float* xrow = Xsrc + (size_t)(GATHER ? g_perm[m0 + rs] : (m0 + rs)) * 256 + h*128;
#pragma unroll
    for (int q8 = 0; q8 < 16; q8++){
        float4 a = *(const float4*)(xrow + q8*8);
        float4 b = *(const float4*)(xrow + q8*8 + 4);
        __half2 h0 = __floats2half2_rn(a.x, a.y), h1 = __floats2half2_rn(a.z, a.w);
        __half2 h2 = __floats2half2_rn(b.x, b.y), h3 = __floats2half2_rn(b.z, b.w);
        *(uint4*)((char*)Ah + r*(ASTRA*2) + h*256 + q8*16) =
            make_uint4(*(uint32_t*)&h0, *(uint32_t*)&h1, *(uint32_t*)&h2, *(uint32_t*)&h3);
    }

    // ---- B prefetch slab 0 (j=3, ic=0) ----
    const size_t wbase = (size_t)bin * 256 * 1024;
    uint4 bh[2];
#pragma unroll
    for (int it = 0; it < 2; it++){
        int idx = it*256 + tid, o = idx >> 2, q = idx & 3;
        bh[it] = *(const uint4*)(WHi + wbase + (size_t)(n0 + o)*1024 + 3*256 + q*8);
    }
#pragma unroll
    for (int it = 0; it < 2; it++){
        int idx = it*256 + tid, o = idx >> 2, q = idx & 3;
        *(uint4*)(smem + OFF_B + o*(BSTR*2) + q*16) = bh[it];
    }
    __syncthreads();

    const int wm = (wid >> 1) * 32, wn = (wid & 1) * 64;
    const int lr = lane >> 2, lk = lane & 3;
    const uint32_t sA = smem_u32(Ah);
    const uint32_t aAddrBase = sA + (uint32_t)(wm + (lane & 15))*(ASTRA*2) + (uint32_t)(lane >> 4)*16;
    const uint32_t bAddrBase = smem_u32(smem + OFF_B)
                             + (uint32_t)(wn + (lane >> 4)*8 + (lane & 7))*(BSTR*2)
                             + (uint32_t)((lane >> 3) & 1)*16;
    float tA[2][2];
#pragma unroll
    for (int mt = 0; mt < 2; mt++){
        tA[mt][0] = spw[(wm + mt*16 + lr)*4 + 1];
        tA[mt][1] = spw[(wm + mt*16 + lr + 8)*4 + 1];
    }

    float acc[2][8][4];
#pragma unroll
    for (int a = 0; a < 2; a++)
#pragma unroll
        for (int b = 0; b < 8; b++)
#pragma unroll
            for (int c = 0; c < 4; c++) acc[a][b][c] = 0.0f;

    for (int s = 0; s < 32; s++){
        const int buf = s & 1;
        const int ic = s & 7;
        // prefetch slab s+1
        if (s < 31){
            const int sn = s + 1;
            const int koff = (3 - (sn >> 3))*256 + (sn & 7)*32;
#pragma unroll
            for (int it = 0; it < 2; it++){
                int idx = it*256 + tid, o = idx >> 2, q = idx & 3;
                bh[it] = *(const uint4*)(WHi + wbase + (size_t)(n0 + o)*1024 + koff + q*8);
            }
        }
        // MMA on slab s
#pragma unroll
        for (int kk = 0; kk < 2; kk++){
            uint32_t af[2][4];
            ldsm4(af[0], aAddrBase + ic*64 + kk*32);
            ldsm4(af[1], aAddrBase + 16*(ASTRA*2) + ic*64 + kk*32);
#pragma unroll
            for (int np = 0; np < 4; np++){
                uint32_t bf[4];
                ldsm4(bf, bAddrBase + buf*BBUF_SZ + np*16*(BSTR*2) + kk*32);
#pragma unroll
                for (int mt = 0; mt < 2; mt++){
                    mma_f16(acc[mt][np*2 + 0], af[mt], bf[0], bf[1]);
                    mma_f16(acc[mt][np*2 + 1], af[mt], bf[2], bf[3]);
                }
            }
        }
        // commit prefetched B into other buffer
        if (s < 31){
#pragma unroll
            for (int it = 0; it < 2; it++){
                int idx = it*256 + tid, o = idx >> 2, q = idx & 3;
                *(uint4*)(smem + OFF_B + (buf ^ 1)*BBUF_SZ + o*(BSTR*2) + q*16) = bh[it];
            }
        }
        // Horner transition at end of each j-block (except last)
        if ((s & 7) == 7 && s < 31){
#pragma unroll
            for (int mt = 0; mt < 2; mt++)
#pragma unroll
                for (int nt = 0; nt < 8; nt++){
                    acc[mt][nt][0] *= tA[mt][0];
                    acc[mt][nt][1] *= tA[mt][0];
                    acc[mt][nt][2] *= tA[mt][1];
                    acc[mt][nt][3] *= tA[mt][1];
                }
        }
        __syncthreads();
    }

    // epilogue: + poly bias, relu, store
#pragma unroll
    for (int mt = 0; mt < 2; mt++){
#pragma unroll
        for (int half = 0; half < 2; half++){
            int rr = wm + mt*16 + lr + half*8;
            if (rr >= rows) continue;
            float pw0 = spw[rr*4+0], pw1 = spw[rr*4+1], pw2 = spw[rr*4+2], pw3 = spw[rr*4+3];
            float* yp = Y + (size_t)(m0 + rr) * 256 + n0;
#pragma unroll
            for (int nt = 0; nt < 8; nt++){
                int col = wn + nt*8 + lk*2;
                float b0 = pw0*pbs[col]     + pw1*pbs[128+col]   + pw2*pbs[256+col]   + pw3*pbs[384+col];
                float b1 = pw0*pbs[col+1]   + pw1*pbs[128+col+1] + pw2*pbs[256+col+1] + pw3*pbs[384+col+1];
                float v0 = acc[mt][nt][half*2 + 0] + b0;
                float v1 = acc[mt][nt][half*2 + 1] + b1;
                if (RELU){ v0 = fmaxf(v0, 0.0f); v1 = fmaxf(v1, 0.0f); }
                *(float2*)(yp + col) = make_float2(v0, v1);
            }
        }
    }
}

// ---------------- head ----------------
__global__ void head_kernel(const float* __restrict__ X,
                            const float* __restrict__ W2, const float* __restrict__ b2,
                            float* __restrict__ out)
{
    const int warp = threadIdx.x >> 5, lane = threadIdx.x & 31;
    const int pos = blockIdx.x * 8 + warp;
    float bb[12];
    basis_eval(g_tp[pos], bb);
    float acc = 0.0f;
#pragma unroll
    for (int ii = 0; ii < 8; ii++){
        const int i = lane + 32*ii;
        float w = 0.0f;
#pragma unroll
        for (int s = 0; s < 12; s++) w = fmaf(bb[s], W2[s*256 + i], w);
        acc = fmaf(X[(size_t)pos*256 + i], w, acc);
    }
#pragma unroll
    for (int off = 16; off; off >>= 1) acc += __shfl_xor_sync(0xffffffffu, acc, off);
    if (lane == 0){
        float bias = 0.0f;
#pragma unroll
        for (int s = 0; s < 12; s++) bias = fmaf(bb[s], b2[s], bias);
        out[g_perm[pos]] = acc + bias;
    }
}

extern "C" void kernel_launch(void* const* d_in, const int* in_sizes, int n_in,
                              void* d_out, int out_size)
{
    const float* T  = (const float*)d_in[0];
    const float* X  = (const float*)d_in[1];
    const float* W0 = (const float*)d_in[2];
    const float* b0 = (const float*)d_in[3];
    const float* W1 = (const float*)d_in[4];
    const float* b1 = (const float*)d_in[5];
    const float* W2 = (const float*)d_in[6];
    const float* b2 = (const float*)d_in[7];
    float* out = (float*)d_out;

    float *buf0, *buf1, *pb0, *pb1;
    __half *wp0, *wp1;
    int* bincnt;
    cudaGetSymbolAddress((void**)&buf0, g_buf0);
    cudaGetSymbolAddress((void**)&buf1, g_buf1);
    cudaGetSymbolAddress((void**)&wp0, g_Wp0);
    cudaGetSymbolAddress((void**)&wp1, g_Wp1);
    cudaGetSymbolAddress((void**)&pb0, g_Pb0);
    cudaGetSymbolAddress((void**)&pb1, g_Pb1);
    cudaGetSymbolAddress((void**)&bincnt, g_bincnt);

    cudaFuncSetAttribute(vc_gemm<true,  true>, cudaFuncAttributeMaxDynamicSharedMemorySize, SMEM_SZ);
    cudaFuncSetAttribute(vc_gemm<false, true>, cudaFuncAttributeMaxDynamicSharedMemorySize, SMEM_SZ);

    cudaMemsetAsync(bincnt, 0, NBINS * sizeof(int), 0);
    bins_hist<<<64, 512>>>(T);
    bins_scan<<<1, 32>>>();
    bins_scatter<<<64, 512>>>(T);
    transpose_w<<<dim3(8, 96, 2), dim3(32, 8)>>>(W0, W1);
    prep_all<<<dim3(257, 2), 256>>>(b0, b1);

    dim3 grid(MAXTILES, 2);
    vc_gemm<true,  true><<<grid, 256, SMEM_SZ>>>(X,    wp0, pb0, buf0);
    vc_gemm<false, true><<<grid, 256, SMEM_SZ>>>(buf0, wp1, pb1, buf1);
    head_kernel<<<NROWS / 8, 256>>>(buf1, W2, b2, out);
}